// round 3
// baseline (speedup 1.0000x reference)
#include <cuda_runtime.h>
#include <cuda_fp16.h>
#include <cstdint>
#include <math.h>

#define NTOK 8192
#define DDIM 2048
#define HDIM 8192
#define ODIM 2048
#define NEXP 8
#define MAXSLOTS (NTOK * 2)

// ---------------- device scratch (static: no allocations allowed) ----------------
__device__ __half g_h[(size_t)(MAXSLOTS + 128) * HDIM];   // fp16 hidden acts, padded tail
__device__ int    g_slot_token[MAXSLOTS];
__device__ float  g_slot_w[MAXSLOTS];
__device__ int    g_tok_e[NTOK * 2];
__device__ float  g_tok_w[NTOK * 2];
__device__ int    g_counts[NEXP];
__device__ int    g_offsets[NEXP + 1];
__device__ float  g_sumP[NEXP];

// ---------------- small kernels ----------------
__global__ void init_kernel() {
    int t = threadIdx.x;
    if (t < NEXP) { g_counts[t] = 0; g_sumP[t] = 0.f; }
}

__global__ void zero_out_kernel(float* out, long long n) {
    long long i = (long long)blockIdx.x * blockDim.x + threadIdx.x;
    long long stride = (long long)gridDim.x * blockDim.x;
    for (; i < n; i += stride) out[i] = 0.f;
}

// Router: one warp per token. gate logits (8 dots over D=2048), softmax, top-2,
// renormalized weights; accumulate sum of gate probs for lb_loss.
__global__ void router_kernel(const float* __restrict__ x,
                              const float* __restrict__ gW,
                              const float* __restrict__ gb) {
    __shared__ float sP[NEXP];
    int tid = threadIdx.x, lane = tid & 31, warp = tid >> 5;
    if (tid < NEXP) sP[tid] = 0.f;
    __syncthreads();

    int n = blockIdx.x * 8 + warp;  // grid sized exactly: always valid
    float acc[NEXP];
#pragma unroll
    for (int e = 0; e < NEXP; e++) acc[e] = 0.f;
    const float* xr = x + (size_t)n * DDIM;
    for (int d = lane; d < DDIM; d += 32) {
        float xv = xr[d];
        const float4* g = reinterpret_cast<const float4*>(gW + (size_t)d * NEXP);
        float4 g0 = g[0], g1 = g[1];
        acc[0] += xv * g0.x; acc[1] += xv * g0.y; acc[2] += xv * g0.z; acc[3] += xv * g0.w;
        acc[4] += xv * g1.x; acc[5] += xv * g1.y; acc[6] += xv * g1.z; acc[7] += xv * g1.w;
    }
#pragma unroll
    for (int e = 0; e < NEXP; e++) {
        float v = acc[e];
#pragma unroll
        for (int o = 16; o > 0; o >>= 1) v += __shfl_xor_sync(0xffffffffu, v, o);
        acc[e] = v;
    }
    if (lane == 0) {
        float p[NEXP];
        float m = -1e30f;
#pragma unroll
        for (int e = 0; e < NEXP; e++) { p[e] = acc[e] + gb[e]; m = fmaxf(m, p[e]); }
        float s = 0.f;
#pragma unroll
        for (int e = 0; e < NEXP; e++) { p[e] = expf(p[e] - m); s += p[e]; }
        float inv = 1.f / s;
#pragma unroll
        for (int e = 0; e < NEXP; e++) { p[e] *= inv; atomicAdd(&sP[e], p[e]); }
        int i0 = 0;
#pragma unroll
        for (int e = 1; e < NEXP; e++) if (p[e] > p[i0]) i0 = e;
        int i1 = (i0 == 0) ? 1 : 0;
#pragma unroll
        for (int e = 0; e < NEXP; e++) if (e != i0 && p[e] > p[i1]) i1 = e;
        float g0 = p[i0], g1 = p[i1], winv = 1.f / (g0 + g1);
        g_tok_e[2 * n] = i0;  g_tok_e[2 * n + 1] = i1;
        g_tok_w[2 * n] = g0 * winv;  g_tok_w[2 * n + 1] = g1 * winv;
        atomicAdd(&g_counts[i0], 1); atomicAdd(&g_counts[i1], 1);
    }
    __syncthreads();
    if (tid < NEXP) atomicAdd(&g_sumP[tid], sP[tid]);
}

// offsets (E=8 exclusive scan) + lb_loss
__global__ void setup_kernel(float* __restrict__ out, long long lbIdx) {
    if (threadIdx.x == 0 && blockIdx.x == 0) {
        int off = 0;
#pragma unroll
        for (int e = 0; e < NEXP; e++) { g_offsets[e] = off; off += g_counts[e]; }
        g_offsets[NEXP] = off;
        float lb = 0.f;
#pragma unroll
        for (int e = 0; e < NEXP; e++) {
            float P = g_sumP[e] / (float)NTOK;
            lb += P * P;
        }
        out[lbIdx] = lb * (float)NEXP;
    }
}

// Deterministic compaction: one block per expert, block-wide scan over tokens.
__global__ void assign_kernel() {
    const int e = blockIdx.x;
    const int tid = threadIdx.x;
    __shared__ int svals[256];
    __shared__ int sbase;
    if (tid == 0) sbase = g_offsets[e];
    __syncthreads();
    for (int t0 = 0; t0 < NTOK; t0 += 256) {
        int n = t0 + tid;
        int sel = 0; float w = 0.f;
        int e0 = g_tok_e[2 * n], e1 = g_tok_e[2 * n + 1];
        if (e0 == e)      { sel = 1; w = g_tok_w[2 * n]; }
        else if (e1 == e) { sel = 1; w = g_tok_w[2 * n + 1]; }
        svals[tid] = sel;
        __syncthreads();
#pragma unroll
        for (int o = 1; o < 256; o <<= 1) {
            int t = (tid >= o) ? svals[tid - o] : 0;
            __syncthreads();
            svals[tid] += t;
            __syncthreads();
        }
        if (sel) {
            int pos = sbase + svals[tid] - 1;
            g_slot_token[pos] = n;
            g_slot_w[pos] = w;
        }
        int total = svals[255];
        __syncthreads();
        if (tid == 0) sbase += total;
        __syncthreads();
    }
}

// ---------------- GEMM (mma.sync m16n8k16 fp16 -> fp32) ----------------
#define BM 128
#define BN 128
#define BK 32
#define LDS_STRIDE 40  // halves; 80B row stride -> conflict-free ldmatrix

__device__ __forceinline__ void ldsm4(uint32_t& r0, uint32_t& r1, uint32_t& r2, uint32_t& r3,
                                      uint32_t addr) {
    asm volatile("ldmatrix.sync.aligned.m8n8.x4.shared.b16 {%0,%1,%2,%3}, [%4];\n"
                 : "=r"(r0), "=r"(r1), "=r"(r2), "=r"(r3) : "r"(addr));
}

__device__ __forceinline__ void mma16816(float* d, const uint32_t* a, const uint32_t* b) {
    asm volatile(
        "mma.sync.aligned.m16n8k16.row.col.f32.f16.f16.f32 "
        "{%0,%1,%2,%3},{%4,%5,%6,%7},{%8,%9},{%0,%1,%2,%3};\n"
        : "+f"(d[0]), "+f"(d[1]), "+f"(d[2]), "+f"(d[3])
        : "r"(a[0]), "r"(a[1]), "r"(a[2]), "r"(a[3]), "r"(b[0]), "r"(b[1]));
}

// MODE 0: h = relu(gather(x) @ fc1_W[e]^T + b1)  -> g_h (fp16)
// MODE 1: y = h @ fc2_W[e]^T + b2; out[token] += w * y (atomicAdd)
template <int MODE>
__global__ void __launch_bounds__(256) ffn_gemm(const float* __restrict__ xin,
                                                const float* __restrict__ Wbase,
                                                const float* __restrict__ bbase,
                                                float* __restrict__ out) {
    constexpr int KDIM = (MODE == 0) ? DDIM : HDIM;
    constexpr int NDIM = (MODE == 0) ? HDIM : ODIM;
    const int e = blockIdx.z;
    const int cnt = __ldg(&g_counts[e]);
    const int mtile = blockIdx.y;
    if (mtile * BM >= cnt) return;
    const int ntile = blockIdx.x;
    const int off = __ldg(&g_offsets[e]);

    __shared__ __align__(16) __half As[2][BM * LDS_STRIDE];
    __shared__ __align__(16) __half Bs[2][BN * LDS_STRIDE];

    const int tid = threadIdx.x;
    const int lane = tid & 31;
    const int warp = tid >> 5;
    const int wm = warp & 1;   // warp row (x64)
    const int wn = warp >> 1;  // warp col (x32)

    const float* Wexp = Wbase + (size_t)e * NDIM * KDIM;
    const float* aPtrF[4];
    const __half* aPtrH[4];
    const float* bPtr[4];
    int arow[4], ac4[4];
#pragma unroll
    for (int i = 0; i < 4; i++) {
        int id = tid + i * 256;
        int row = id >> 3;
        int c4 = id & 7;
        arow[i] = row; ac4[i] = c4;
        int m = mtile * BM + row;
        if constexpr (MODE == 0) {
            int mm = (m < cnt) ? m : (cnt - 1);
            int token = g_slot_token[off + mm];
            aPtrF[i] = xin + (size_t)token * KDIM + c4 * 4;
            aPtrH[i] = nullptr;
        } else {
            aPtrH[i] = g_h + (size_t)(off + m) * KDIM + c4 * 4;
            aPtrF[i] = nullptr;
        }
        int nrow = ntile * BN + row;
        bPtr[i] = Wexp + (size_t)nrow * KDIM + c4 * 4;
    }

    uint2 ra[4], rb[4];
    auto load = [&](int k0) {
#pragma unroll
        for (int i = 0; i < 4; i++) {
            if constexpr (MODE == 0) {
                float4 v = *reinterpret_cast<const float4*>(aPtrF[i] + k0);
                __half2 h0 = __floats2half2_rn(v.x, v.y);
                __half2 h1 = __floats2half2_rn(v.z, v.w);
                ra[i].x = *reinterpret_cast<uint32_t*>(&h0);
                ra[i].y = *reinterpret_cast<uint32_t*>(&h1);
            } else {
                ra[i] = *reinterpret_cast<const uint2*>(aPtrH[i] + k0);
            }
            float4 w = *reinterpret_cast<const float4*>(bPtr[i] + k0);
            __half2 q0 = __floats2half2_rn(w.x, w.y);
            __half2 q1 = __floats2half2_rn(w.z, w.w);
            rb[i].x = *reinterpret_cast<uint32_t*>(&q0);
            rb[i].y = *reinterpret_cast<uint32_t*>(&q1);
        }
    };
    auto store = [&](int buf) {
#pragma unroll
        for (int i = 0; i < 4; i++) {
            *reinterpret_cast<uint2*>(&As[buf][arow[i] * LDS_STRIDE + ac4[i] * 4]) = ra[i];
            *reinterpret_cast<uint2*>(&Bs[buf][arow[i] * LDS_STRIDE + ac4[i] * 4]) = rb[i];
        }
    };

    float acc[4][4][4];
#pragma unroll
    for (int mi = 0; mi < 4; mi++)
#pragma unroll
        for (int ni = 0; ni < 4; ni++)
#pragma unroll
            for (int j = 0; j < 4; j++) acc[mi][ni][j] = 0.f;

    load(0); store(0); __syncthreads();

    const int kTiles = KDIM / BK;
    for (int kt = 0; kt < kTiles; kt++) {
        int buf = kt & 1;
        if (kt + 1 < kTiles) load((kt + 1) * BK);
#pragma unroll
        for (int kk = 0; kk < 2; kk++) {
            uint32_t af[4][4], bf[4][2];
#pragma unroll
            for (int mi = 0; mi < 4; mi++) {
                const __half* p = &As[buf][(wm * 64 + mi * 16 + (lane & 15)) * LDS_STRIDE +
                                           kk * 16 + ((lane >> 4) << 3)];
                ldsm4(af[mi][0], af[mi][1], af[mi][2], af[mi][3],
                      (uint32_t)__cvta_generic_to_shared(p));
            }
#pragma unroll
            for (int pr = 0; pr < 2; pr++) {
                const __half* p = &Bs[buf][(wn * 32 + pr * 16 + ((lane >> 4) << 3) + (lane & 7)) *
                                               LDS_STRIDE +
                                           kk * 16 + (((lane >> 3) & 1) << 3)];
                ldsm4(bf[pr * 2][0], bf[pr * 2][1], bf[pr * 2 + 1][0], bf[pr * 2 + 1][1],
                      (uint32_t)__cvta_generic_to_shared(p));
            }
#pragma unroll
            for (int mi = 0; mi < 4; mi++)
#pragma unroll
                for (int ni = 0; ni < 4; ni++) mma16816(acc[mi][ni], af[mi], bf[ni]);
        }
        if (kt + 1 < kTiles) store(buf ^ 1);
        __syncthreads();
    }

    const int lrow = lane >> 2;
    const int lcol = (lane & 3) * 2;
#pragma unroll
    for (int mi = 0; mi < 4; mi++) {
#pragma unroll
        for (int hh = 0; hh < 2; hh++) {
            int rloc = wm * 64 + mi * 16 + lrow + hh * 8;
            int gm = mtile * BM + rloc;
            if (gm < cnt) {
                if constexpr (MODE == 0) {
                    size_t hbase = (size_t)(off + gm) * HDIM;
#pragma unroll
                    for (int ni = 0; ni < 4; ni++) {
                        int col = ntile * BN + wn * 32 + ni * 8 + lcol;
                        float c0 = acc[mi][ni][hh * 2 + 0] + bbase[e * NDIM + col];
                        float c1 = acc[mi][ni][hh * 2 + 1] + bbase[e * NDIM + col + 1];
                        c0 = fmaxf(c0, 0.f); c1 = fmaxf(c1, 0.f);
                        __half2 hv = __floats2half2_rn(c0, c1);
                        *reinterpret_cast<__half2*>(&g_h[hbase + col]) = hv;
                    }
                } else {
                    int token = g_slot_token[off + gm];
                    float w = g_slot_w[off + gm];
                    float* orow = out + (size_t)token * ODIM;
#pragma unroll
                    for (int ni = 0; ni < 4; ni++) {
                        int col = ntile * BN + wn * 32 + ni * 8 + lcol;
                        float c0 = acc[mi][ni][hh * 2 + 0] + bbase[e * NDIM + col];
                        float c1 = acc[mi][ni][hh * 2 + 1] + bbase[e * NDIM + col + 1];
                        atomicAdd(&orow[col], w * c0);
                        atomicAdd(&orow[col + 1], w * c1);
                    }
                }
            }
        }
    }
}

// ---------------- launch ----------------
extern "C" void kernel_launch(void* const* d_in, const int* in_sizes, int n_in,
                              void* d_out, int out_size) {
    const float* x  = (const float*)d_in[0];
    const float* gW = (const float*)d_in[1];
    const float* gb = (const float*)d_in[2];
    const float* W1 = (const float*)d_in[3];
    const float* b1 = (const float*)d_in[4];
    const float* W2 = (const float*)d_in[5];
    const float* b2 = (const float*)d_in[6];
    float* out = (float*)d_out;

    zero_out_kernel<<<2048, 256>>>(out, (long long)out_size);
    init_kernel<<<1, 32>>>();
    router_kernel<<<NTOK / 8, 256>>>(x, gW, gb);
    setup_kernel<<<1, 1>>>(out, (long long)out_size - 1);
    assign_kernel<<<NEXP, 256>>>();
    ffn_gemm<0><<<dim3(HDIM / BN, 64, NEXP), 256>>>(x, W1, b1, nullptr);
    ffn_gemm<1><<<dim3(ODIM / BN, 64, NEXP), 256>>>(nullptr, W2, b2, out);
}

// round 7
// speedup vs baseline: 1.2596x; 1.2596x over previous
#include <cuda_runtime.h>
#include <cuda_fp16.h>
#include <cstdint>
#include <math.h>

#define NTOK 8192
#define DDIM 2048
#define HDIM 8192
#define ODIM 2048
#define NEXP 8
#define MAXSLOTS (NTOK * 2)
#define SLOTPAD (MAXSLOTS + 256)

// ---------------- device scratch (static: no allocations allowed) ----------------
// Single shared fp16 weight buffer: W1 and W2 are converted into it sequentially
// (stream order: convert W1 -> GEMM1 -> convert W2 -> GEMM2), halving weight scratch.
__device__ __align__(16) __half g_wbuf[(size_t)NEXP * HDIM * DDIM]; // 268 MB
__device__ __align__(16) __half g_xa[(size_t)SLOTPAD * DDIM];       // gathered x, fp16
__device__ __align__(16) __half g_h [(size_t)SLOTPAD * HDIM];       // hidden acts, fp16
__device__ int    g_slot_token[MAXSLOTS];
__device__ float  g_slot_w[MAXSLOTS];
__device__ int    g_tok_e[NTOK * 2];
__device__ float  g_tok_w[NTOK * 2];
__device__ int    g_counts[NEXP];
__device__ int    g_offsets[NEXP + 1];
__device__ float  g_sumP[NEXP];

// ---------------- small kernels (verified passing in R3) ----------------
__global__ void init_kernel() {
    int t = threadIdx.x;
    if (t < NEXP) { g_counts[t] = 0; g_sumP[t] = 0.f; }
}

__global__ void zero_out_kernel(float* out, long long n) {
    long long i = (long long)blockIdx.x * blockDim.x + threadIdx.x;
    long long stride = (long long)gridDim.x * blockDim.x;
    for (; i < n; i += stride) out[i] = 0.f;
}

__global__ void router_kernel(const float* __restrict__ x,
                              const float* __restrict__ gW,
                              const float* __restrict__ gb) {
    __shared__ float sP[NEXP];
    int tid = threadIdx.x, lane = tid & 31, warp = tid >> 5;
    if (tid < NEXP) sP[tid] = 0.f;
    __syncthreads();

    int n = blockIdx.x * 8 + warp;
    float acc[NEXP];
#pragma unroll
    for (int e = 0; e < NEXP; e++) acc[e] = 0.f;
    const float* xr = x + (size_t)n * DDIM;
    for (int d = lane; d < DDIM; d += 32) {
        float xv = xr[d];
        const float4* g = reinterpret_cast<const float4*>(gW + (size_t)d * NEXP);
        float4 g0 = g[0], g1 = g[1];
        acc[0] += xv * g0.x; acc[1] += xv * g0.y; acc[2] += xv * g0.z; acc[3] += xv * g0.w;
        acc[4] += xv * g1.x; acc[5] += xv * g1.y; acc[6] += xv * g1.z; acc[7] += xv * g1.w;
    }
#pragma unroll
    for (int e = 0; e < NEXP; e++) {
        float v = acc[e];
#pragma unroll
        for (int o = 16; o > 0; o >>= 1) v += __shfl_xor_sync(0xffffffffu, v, o);
        acc[e] = v;
    }
    if (lane == 0) {
        float p[NEXP];
        float m = -1e30f;
#pragma unroll
        for (int e = 0; e < NEXP; e++) { p[e] = acc[e] + gb[e]; m = fmaxf(m, p[e]); }
        float s = 0.f;
#pragma unroll
        for (int e = 0; e < NEXP; e++) { p[e] = expf(p[e] - m); s += p[e]; }
        float inv = 1.f / s;
#pragma unroll
        for (int e = 0; e < NEXP; e++) { p[e] *= inv; atomicAdd(&sP[e], p[e]); }
        int i0 = 0;
#pragma unroll
        for (int e = 1; e < NEXP; e++) if (p[e] > p[i0]) i0 = e;
        int i1 = (i0 == 0) ? 1 : 0;
#pragma unroll
        for (int e = 0; e < NEXP; e++) if (e != i0 && p[e] > p[i1]) i1 = e;
        float g0 = p[i0], g1 = p[i1], winv = 1.f / (g0 + g1);
        g_tok_e[2 * n] = i0;  g_tok_e[2 * n + 1] = i1;
        g_tok_w[2 * n] = g0 * winv;  g_tok_w[2 * n + 1] = g1 * winv;
        atomicAdd(&g_counts[i0], 1); atomicAdd(&g_counts[i1], 1);
    }
    __syncthreads();
    if (tid < NEXP) atomicAdd(&g_sumP[tid], sP[tid]);
}

__global__ void setup_kernel(float* __restrict__ out, long long lbIdx) {
    if (threadIdx.x == 0 && blockIdx.x == 0) {
        int off = 0;
#pragma unroll
        for (int e = 0; e < NEXP; e++) { g_offsets[e] = off; off += g_counts[e]; }
        g_offsets[NEXP] = off;
        float lb = 0.f;
#pragma unroll
        for (int e = 0; e < NEXP; e++) {
            float P = g_sumP[e] / (float)NTOK;
            lb += P * P;
        }
        out[lbIdx] = lb * (float)NEXP;
    }
}

__global__ void assign_kernel() {
    const int e = blockIdx.x;
    const int tid = threadIdx.x;
    __shared__ int svals[256];
    __shared__ int sbase;
    if (tid == 0) sbase = g_offsets[e];
    __syncthreads();
    for (int t0 = 0; t0 < NTOK; t0 += 256) {
        int n = t0 + tid;
        int sel = 0; float w = 0.f;
        int e0 = g_tok_e[2 * n], e1 = g_tok_e[2 * n + 1];
        if (e0 == e)      { sel = 1; w = g_tok_w[2 * n]; }
        else if (e1 == e) { sel = 1; w = g_tok_w[2 * n + 1]; }
        svals[tid] = sel;
        __syncthreads();
#pragma unroll
        for (int o = 1; o < 256; o <<= 1) {
            int t = (tid >= o) ? svals[tid - o] : 0;
            __syncthreads();
            svals[tid] += t;
            __syncthreads();
        }
        if (sel) {
            int pos = sbase + svals[tid] - 1;
            g_slot_token[pos] = n;
            g_slot_w[pos] = w;
        }
        int total = svals[255];
        __syncthreads();
        if (tid == 0) sbase += total;
        __syncthreads();
    }
}

// ---------------- preconvert kernels ----------------
__global__ void convert_w_kernel(const float* __restrict__ src, __half* __restrict__ dst,
                                 size_t n8) {
    size_t i = (size_t)blockIdx.x * blockDim.x + threadIdx.x;
    size_t stride = (size_t)gridDim.x * blockDim.x;
    for (; i < n8; i += stride) {
        const float4* s = reinterpret_cast<const float4*>(src + i * 8);
        float4 v0 = s[0], v1 = s[1];
        __half2 h0 = __floats2half2_rn(v0.x, v0.y);
        __half2 h1 = __floats2half2_rn(v0.z, v0.w);
        __half2 h2 = __floats2half2_rn(v1.x, v1.y);
        __half2 h3 = __floats2half2_rn(v1.z, v1.w);
        uint2* d = reinterpret_cast<uint2*>(dst + i * 8);
        d[0] = make_uint2(*(uint32_t*)&h0, *(uint32_t*)&h1);
        d[1] = make_uint2(*(uint32_t*)&h2, *(uint32_t*)&h3);
    }
}

__global__ void gather_x_kernel(const float* __restrict__ x) {
    int slot = blockIdx.x;
    int token = g_slot_token[slot];
    const float* src = x + (size_t)token * DDIM;
    __half* dst = g_xa + (size_t)slot * DDIM;
    int t = threadIdx.x;
#pragma unroll
    for (int i = 0; i < 2; i++) {
        int c = (t + i * 256) * 4;
        float4 v = *reinterpret_cast<const float4*>(src + c);
        __half2 h0 = __floats2half2_rn(v.x, v.y);
        __half2 h1 = __floats2half2_rn(v.z, v.w);
        *reinterpret_cast<uint2*>(dst + c) = make_uint2(*(uint32_t*)&h0, *(uint32_t*)&h1);
    }
}

// ---------------- HMMA GEMM: BM=256 BN=128 BK=32, 512 thr, 4-stage cp.async ----------------
#define BM 256
#define BN 128
#define BK 32
#define STAGES 4
#define STRIDE 40                       // halves; 80B rows -> conflict-free ldsm
#define A_STG (BM * STRIDE * 2)         // 20480 B
#define B_STG (BN * STRIDE * 2)         // 10240 B
#define GEMM_SMEM (STAGES * (A_STG + B_STG))  // 122880 B

__device__ __forceinline__ uint32_t smem_u32(const void* p) {
    uint32_t a;
    asm("{ .reg .u64 t; cvta.to.shared.u64 t, %1; cvt.u32.u64 %0, t; }" : "=r"(a) : "l"(p));
    return a;
}
__device__ __forceinline__ void cpa16(uint32_t dst, const void* src) {
    asm volatile("cp.async.cg.shared.global [%0], [%1], 16;" :: "r"(dst), "l"(src));
}
__device__ __forceinline__ void cpa_commit() {
    asm volatile("cp.async.commit_group;" ::: "memory");
}
__device__ __forceinline__ void cpa_wait2() {
    asm volatile("cp.async.wait_group 2;" ::: "memory");
}
__device__ __forceinline__ void ldsm4(uint32_t& r0, uint32_t& r1, uint32_t& r2, uint32_t& r3,
                                      uint32_t addr) {
    asm volatile("ldmatrix.sync.aligned.m8n8.x4.shared.b16 {%0,%1,%2,%3}, [%4];\n"
                 : "=r"(r0), "=r"(r1), "=r"(r2), "=r"(r3) : "r"(addr));
}
__device__ __forceinline__ void mma16816(float* d, const uint32_t* a, const uint32_t* b) {
    asm volatile(
        "mma.sync.aligned.m16n8k16.row.col.f32.f16.f16.f32 "
        "{%0,%1,%2,%3},{%4,%5,%6,%7},{%8,%9},{%0,%1,%2,%3};\n"
        : "+f"(d[0]), "+f"(d[1]), "+f"(d[2]), "+f"(d[3])
        : "r"(a[0]), "r"(a[1]), "r"(a[2]), "r"(a[3]), "r"(b[0]), "r"(b[1]));
}

// MODE 0: h = relu(A @ W1[e]^T + b1) -> g_h (fp16)
// MODE 1: out[token] += w * (A @ W2[e]^T + b2)   (atomicAdd; 2 adds/element total)
template <int MODE>
__global__ void __launch_bounds__(512, 1) ffn_gemm(const __half* __restrict__ Abase,
                                                   const __half* __restrict__ Wbase,
                                                   const float* __restrict__ bbase,
                                                   float* __restrict__ out) {
    constexpr int KDIM = (MODE == 0) ? DDIM : HDIM;
    constexpr int NDIM = (MODE == 0) ? HDIM : ODIM;
    constexpr int KT = KDIM / BK;

    const int e = blockIdx.z;
    const int cnt = g_counts[e];
    const int mtile = blockIdx.y;
    if (mtile * BM >= cnt) return;
    const int ntile = blockIdx.x;
    const int off = g_offsets[e];

    extern __shared__ __align__(16) char smem[];
    const uint32_t sa = smem_u32(smem);            // A stages at sa + s*A_STG
    const uint32_t sbB = sa + STAGES * A_STG;      // B stages

    const int tid = threadIdx.x;
    const int lane = tid & 31;
    const int warp = tid >> 5;
    const int wm = warp & 3;   // 4 warp-rows x 64
    const int wn = warp >> 2;  // 4 warp-cols x 32

    const __half* Aexp = Abase + (size_t)(off + mtile * BM) * KDIM;
    const __half* Wexp = Wbase + (size_t)e * NDIM * KDIM + (size_t)(ntile * BN) * KDIM;

    // copy maps: chunks of 8 halves (16B). A: 256 rows x 4 chunks = 1024; B: 128 x 4 = 512.
    const int arow0 = tid >> 2, ac8 = tid & 3;          // A chunk 0 (tid), chunk 1 = tid+512
    const int arow1 = (tid + 512) >> 2;
    const int brow = tid >> 2;                          // B chunk (tid)

    auto copy_stage = [&](int kt, int s) {
        const int ko = kt * BK + ac8 * 8;
        cpa16(sa + s * A_STG + arow0 * 80 + ac8 * 16, Aexp + (size_t)arow0 * KDIM + ko);
        cpa16(sa + s * A_STG + arow1 * 80 + ac8 * 16, Aexp + (size_t)arow1 * KDIM + ko);
        cpa16(sbB + s * B_STG + brow * 80 + ac8 * 16, Wexp + (size_t)brow * KDIM + ko);
    };

    float acc[4][4][4];
#pragma unroll
    for (int mi = 0; mi < 4; mi++)
#pragma unroll
        for (int ni = 0; ni < 4; ni++)
#pragma unroll
            for (int j = 0; j < 4; j++) acc[mi][ni][j] = 0.f;

#pragma unroll
    for (int i = 0; i < STAGES - 1; i++) {
        if (i < KT) copy_stage(i, i);
        cpa_commit();
    }

    const uint32_t aFragBase = sa + (wm * 64 + (lane & 15)) * 80 + ((lane >> 4) << 3) * 2;
    const uint32_t bFragBase =
        sbB + (wn * 32 + ((lane >> 4) << 3) + (lane & 7)) * 80 + (((lane >> 3) & 1) << 3) * 2;

    for (int kt = 0; kt < KT; kt++) {
        const int buf = kt & (STAGES - 1);
        cpa_wait2();
        __syncthreads();
#pragma unroll
        for (int kk = 0; kk < 2; kk++) {
            uint32_t af[4][4], bf[4][2];
#pragma unroll
            for (int mi = 0; mi < 4; mi++)
                ldsm4(af[mi][0], af[mi][1], af[mi][2], af[mi][3],
                      aFragBase + buf * A_STG + mi * 16 * 80 + kk * 32);
#pragma unroll
            for (int pr = 0; pr < 2; pr++)
                ldsm4(bf[pr * 2][0], bf[pr * 2][1], bf[pr * 2 + 1][0], bf[pr * 2 + 1][1],
                      bFragBase + buf * B_STG + pr * 16 * 80 + kk * 32);
#pragma unroll
            for (int mi = 0; mi < 4; mi++)
#pragma unroll
                for (int ni = 0; ni < 4; ni++) mma16816(acc[mi][ni], af[mi], bf[ni]);
        }
        __syncthreads();
        if (kt + STAGES - 1 < KT) copy_stage(kt + STAGES - 1, (kt + STAGES - 1) & (STAGES - 1));
        cpa_commit();
    }

    // ---- epilogue ----
    const int lrow = lane >> 2;
    const int lcol = (lane & 3) * 2;
#pragma unroll
    for (int mi = 0; mi < 4; mi++) {
#pragma unroll
        for (int hh = 0; hh < 2; hh++) {
            int rloc = wm * 64 + mi * 16 + lrow + hh * 8;
            int gm = mtile * BM + rloc;
            if (gm < cnt) {
                if constexpr (MODE == 0) {
                    __half* hrow = g_h + (size_t)(off + gm) * HDIM;
#pragma unroll
                    for (int ni = 0; ni < 4; ni++) {
                        int col = ntile * BN + wn * 32 + ni * 8 + lcol;
                        float c0 = acc[mi][ni][hh * 2 + 0] + bbase[e * NDIM + col];
                        float c1 = acc[mi][ni][hh * 2 + 1] + bbase[e * NDIM + col + 1];
                        __half2 hv = __floats2half2_rn(fmaxf(c0, 0.f), fmaxf(c1, 0.f));
                        *reinterpret_cast<__half2*>(hrow + col) = hv;
                    }
                } else {
                    float w = g_slot_w[off + gm];
                    float* orow = out + (size_t)g_slot_token[off + gm] * ODIM;
#pragma unroll
                    for (int ni = 0; ni < 4; ni++) {
                        int col = ntile * BN + wn * 32 + ni * 8 + lcol;
                        float c0 = acc[mi][ni][hh * 2 + 0] + bbase[e * NDIM + col];
                        float c1 = acc[mi][ni][hh * 2 + 1] + bbase[e * NDIM + col + 1];
                        atomicAdd(&orow[col], w * c0);
                        atomicAdd(&orow[col + 1], w * c1);
                    }
                }
            }
        }
    }
}

// ---------------- launch ----------------
extern "C" void kernel_launch(void* const* d_in, const int* in_sizes, int n_in,
                              void* d_out, int out_size) {
    const float* x  = (const float*)d_in[0];
    const float* gW = (const float*)d_in[1];
    const float* gb = (const float*)d_in[2];
    const float* W1 = (const float*)d_in[3];
    const float* b1 = (const float*)d_in[4];
    const float* W2 = (const float*)d_in[5];
    const float* b2 = (const float*)d_in[6];
    float* out = (float*)d_out;

    // Unconditional every call (no static guards — harness determinism rule).
    cudaFuncSetAttribute(ffn_gemm<0>, cudaFuncAttributeMaxDynamicSharedMemorySize, GEMM_SMEM);
    cudaFuncSetAttribute(ffn_gemm<1>, cudaFuncAttributeMaxDynamicSharedMemorySize, GEMM_SMEM);

    zero_out_kernel<<<2048, 256>>>(out, (long long)out_size);
    init_kernel<<<1, 32>>>();
    router_kernel<<<NTOK / 8, 256>>>(x, gW, gb);
    setup_kernel<<<1, 1>>>(out, (long long)out_size - 1);
    assign_kernel<<<NEXP, 256>>>();
    gather_x_kernel<<<MAXSLOTS, 256>>>(x);

    __half* wbuf = nullptr;
    cudaGetSymbolAddress((void**)&wbuf, g_wbuf);
    __half* xad = nullptr; __half* hd = nullptr;
    cudaGetSymbolAddress((void**)&xad, g_xa);
    cudaGetSymbolAddress((void**)&hd, g_h);

    size_t n8w = (size_t)NEXP * HDIM * DDIM / 8;

    // Stream-ordered reuse of the single weight buffer:
    convert_w_kernel<<<4096, 256>>>(W1, wbuf, n8w);
    ffn_gemm<0><<<dim3(HDIM / BN, MAXSLOTS / BM, NEXP), 512, GEMM_SMEM>>>(xad, wbuf, b1, nullptr);
    convert_w_kernel<<<4096, 256>>>(W2, wbuf, n8w);
    ffn_gemm<1><<<dim3(ODIM / BN, MAXSLOTS / BM, NEXP), 512, GEMM_SMEM>>>(hd, wbuf, b2, out);
}